// round 1
// baseline (speedup 1.0000x reference)
#include <cuda_runtime.h>
#include <math.h>

#define D_MODEL 1024
#define D_INNER 2048
#define NT      1024
#define NB      2
#define ROWS    (NB*NT)      // 2048 token rows
#define DSTATE  64

// ---------------- scratch (device globals; no allocation) ----------------
__device__ float g_xn[ROWS*D_MODEL];        // 8 MB  layernorm output
__device__ float g_xz[ROWS*2*D_INNER];      // 32 MB xz = xn @ W_in  (xp | z)
__device__ float g_xc[ROWS*D_INNER];        // 16 MB conv+silu output
__device__ float g_bc[ROWS*2*DSTATE];       // 1 MB  B_proj | C_proj
__device__ float g_dtm[ROWS];               //       row-sum of softplus(dt)
__device__ float g_yg[ROWS*D_INNER];        // 16 MB gated y before W_out

// ---------------- layernorm ----------------
__global__ __launch_bounds__(256) void k_ln(const float* __restrict__ x,
                                            const float* __restrict__ g,
                                            const float* __restrict__ bb) {
    int row = blockIdx.x;
    int tid = threadIdx.x;
    const float4 v = *(const float4*)(x + (size_t)row*D_MODEL + tid*4);
    float s = v.x+v.y+v.z+v.w;
    float q = v.x*v.x+v.y*v.y+v.z*v.z+v.w*v.w;
    #pragma unroll
    for (int o=16;o;o>>=1){ s += __shfl_xor_sync(~0u,s,o); q += __shfl_xor_sync(~0u,q,o); }
    __shared__ float ss[8], qq[8];
    int w = tid>>5;
    if ((tid&31)==0){ ss[w]=s; qq[w]=q; }
    __syncthreads();
    s = 0.f; q = 0.f;
    #pragma unroll
    for (int j=0;j<8;j++){ s += ss[j]; q += qq[j]; }
    float mu  = s*(1.f/(float)D_MODEL);
    float var = q*(1.f/(float)D_MODEL) - mu*mu;
    float inv = rsqrtf(var + 1e-5f);
    float4 gg = *(const float4*)(g  + tid*4);
    float4 b4 = *(const float4*)(bb + tid*4);
    float4 o;
    o.x = (v.x-mu)*inv*gg.x + b4.x;
    o.y = (v.y-mu)*inv*gg.y + b4.y;
    o.z = (v.z-mu)*inv*gg.z + b4.z;
    o.w = (v.w-mu)*inv*gg.w + b4.w;
    *(float4*)(g_xn + (size_t)row*D_MODEL + tid*4) = o;
}

// ---------------- SGEMM: C[M,N] = A[M,K] @ B[K,N] ----------------
// MODE 0: plain store
// MODE 1: softplus(acc + aux[col]) then row-sum atomically into rowsum (no C store)
// MODE 2: store acc + aux[row*N+col] (residual add)
template<int MODE>
__device__ __forceinline__ void sgemm_body(
    const float* __restrict__ A, const float* __restrict__ B,
    float* __restrict__ C, const float* __restrict__ aux,
    float* __restrict__ rowsum, int M, int N, int K)
{
    __shared__ float As[16][128];
    __shared__ float Bs[16][128];
    __shared__ float rs[128];
    const int tid = threadIdx.x;
    const int bx = blockIdx.x, by = blockIdx.y;
    if (MODE==1 && tid < 128) rs[tid] = 0.f;
    const int tx = tid & 15, ty = tid >> 4;
    const int arow = tid >> 2;          // 0..63 (+64 for second)
    const int ak   = (tid & 3) << 2;    // 0,4,8,12
    const int brow = tid >> 5;          // 0..7  (+8 for second)
    const int bcol = (tid & 31) << 2;
    const float* Ab = A + (size_t)by*128*K;
    const float* Bb = B + bx*128;
    float acc[8][8];
    #pragma unroll
    for (int i=0;i<8;i++)
        #pragma unroll
        for (int j=0;j<8;j++) acc[i][j] = 0.f;

    for (int kt=0; kt<K; kt+=16){
        float4 a0 = *(const float4*)(Ab + (size_t)arow*K      + kt + ak);
        float4 a1 = *(const float4*)(Ab + (size_t)(arow+64)*K + kt + ak);
        float4 b0 = *(const float4*)(Bb + (size_t)(kt+brow)*N   + bcol);
        float4 b1 = *(const float4*)(Bb + (size_t)(kt+brow+8)*N + bcol);
        __syncthreads();
        As[ak+0][arow]=a0.x; As[ak+1][arow]=a0.y; As[ak+2][arow]=a0.z; As[ak+3][arow]=a0.w;
        As[ak+0][arow+64]=a1.x; As[ak+1][arow+64]=a1.y; As[ak+2][arow+64]=a1.z; As[ak+3][arow+64]=a1.w;
        *(float4*)&Bs[brow  ][bcol] = b0;
        *(float4*)&Bs[brow+8][bcol] = b1;
        __syncthreads();
        #pragma unroll
        for (int k=0;k<16;k++){
            float ar[8], br[8];
            *(float4*)&ar[0] = *(const float4*)&As[k][ty*8];
            *(float4*)&ar[4] = *(const float4*)&As[k][ty*8+4];
            *(float4*)&br[0] = *(const float4*)&Bs[k][tx*8];
            *(float4*)&br[4] = *(const float4*)&Bs[k][tx*8+4];
            #pragma unroll
            for (int i=0;i<8;i++)
                #pragma unroll
                for (int j=0;j<8;j++)
                    acc[i][j] = fmaf(ar[i], br[j], acc[i][j]);
        }
    }
    const int row0 = by*128 + ty*8;
    const int col0 = bx*128 + tx*8;
    if (MODE==1){
        #pragma unroll
        for (int i=0;i<8;i++){
            float s = 0.f;
            #pragma unroll
            for (int j=0;j<8;j++){
                float v = acc[i][j] + aux[col0+j];
                v = (v > 20.f) ? v : log1pf(__expf(v));
                s += v;
            }
            atomicAdd(&rs[ty*8+i], s);
        }
        __syncthreads();
        if (tid < 128) atomicAdd(&rowsum[by*128 + tid], rs[tid]);
    } else {
        #pragma unroll
        for (int i=0;i<8;i++){
            float4 o0 = make_float4(acc[i][0],acc[i][1],acc[i][2],acc[i][3]);
            float4 o1 = make_float4(acc[i][4],acc[i][5],acc[i][6],acc[i][7]);
            size_t off = (size_t)(row0+i)*N + col0;
            if (MODE==2){
                float4 r0 = *(const float4*)(aux + off);
                float4 r1 = *(const float4*)(aux + off + 4);
                o0.x+=r0.x; o0.y+=r0.y; o0.z+=r0.z; o0.w+=r0.w;
                o1.x+=r1.x; o1.y+=r1.y; o1.z+=r1.z; o1.w+=r1.w;
            }
            *(float4*)(C + off)     = o0;
            *(float4*)(C + off + 4) = o1;
        }
    }
}

__global__ __launch_bounds__(256) void k_gemm_in(const float* __restrict__ W){
    sgemm_body<0>(g_xn, W, g_xz, nullptr, nullptr, ROWS, 2*D_INNER, D_MODEL);
}
__global__ __launch_bounds__(256) void k_gemm_bc(const float* __restrict__ W){
    sgemm_body<0>(g_xc, W, g_bc, nullptr, nullptr, ROWS, 2*DSTATE, D_INNER);
}
__global__ __launch_bounds__(256) void k_gemm_dt(const float* __restrict__ W, const float* __restrict__ bdt){
    sgemm_body<1>(g_xc, W, nullptr, bdt, g_dtm, ROWS, D_INNER, D_INNER);
}
__global__ __launch_bounds__(256) void k_gemm_out(const float* __restrict__ W, const float* __restrict__ x,
                                                  float* __restrict__ out){
    sgemm_body<2>(g_yg, W, out, x, nullptr, ROWS, D_MODEL, D_INNER);
}

// ---------------- depthwise causal conv (width 4) + silu ----------------
__global__ __launch_bounds__(256) void k_conv(const float* __restrict__ cw,
                                              const float* __restrict__ cb){
    int idx = blockIdx.x*256 + threadIdx.x;           // (b,t,i) flat, D_INNER fastest
    if (idx < ROWS) g_dtm[idx] = 0.f;                 // zero the dt row-sum for this replay
    int i = idx & (D_INNER-1);
    int t = (idx >> 11) & (NT-1);
    int b = idx >> 21;
    float4 w = *(const float4*)(cw + i*4);
    float ws[4] = {w.x, w.y, w.z, w.w};
    float acc = cb[i];
    const float* xp = g_xz + (size_t)(b*NT)*(2*D_INNER) + i;   // xp = first half of xz rows
    #pragma unroll
    for (int k=0;k<4;k++){
        int tt = t + k - 3;
        if (tt >= 0) acc += xp[(size_t)tt*(2*D_INNER)] * ws[k];
    }
    float sg = 1.f / (1.f + __expf(-acc));
    g_xc[idx] = acc * sg;
}

// ---------------- sequential SSM scan: one warp per (b, i) ----------------
__global__ __launch_bounds__(256) void k_scan(const float* __restrict__ A_log,
                                              const float* __restrict__ Dp_){
    int wg = (blockIdx.x*blockDim.x + threadIdx.x) >> 5;   // 0..NB*D_INNER-1
    int l  = threadIdx.x & 31;
    int b  = wg >> 11;
    int i  = wg & (D_INNER-1);
    float A0 = -__expf(A_log[i*DSTATE + 2*l]);
    float A1 = -__expf(A_log[i*DSTATE + 2*l + 1]);
    float Dp = Dp_[i];
    float h0 = 0.f, h1 = 0.f;
    const size_t base = (size_t)b*NT;
    const float* bcb = g_bc + base*(2*DSTATE);
    for (int t=0; t<NT; t++){
        float dtm = g_dtm[base + t] * (1.f/(float)D_INNER);
        float xc  = g_xc[(base+t)*D_INNER + i];
        float2 Bv = *(const float2*)(bcb + (size_t)t*(2*DSTATE) + 2*l);
        float2 Cv = *(const float2*)(bcb + (size_t)t*(2*DSTATE) + DSTATE + 2*l);
        float xdt = xc * dtm;
        h0 = __expf(dtm*A0)*h0 + xdt*Bv.x;
        h1 = __expf(dtm*A1)*h1 + xdt*Bv.y;
        float yp = h0*Cv.x + h1*Cv.y;
        #pragma unroll
        for (int o=16;o;o>>=1) yp += __shfl_xor_sync(~0u, yp, o);
        if (l == 0){
            float z  = g_xz[(base+t)*(2*D_INNER) + D_INNER + i];
            float sz = z / (1.f + __expf(-z));
            g_yg[(base+t)*D_INNER + i] = (yp + Dp*xc) * sz;
        }
    }
}

// ---------------- launch ----------------
extern "C" void kernel_launch(void* const* d_in, const int* in_sizes, int n_in,
                              void* d_out, int out_size) {
    const float* x      = (const float*)d_in[0];
    const float* W_in   = (const float*)d_in[1];
    const float* conv_w = (const float*)d_in[2];
    const float* conv_b = (const float*)d_in[3];
    const float* W_x    = (const float*)d_in[4];
    const float* W_dt   = (const float*)d_in[5];
    const float* b_dt   = (const float*)d_in[6];
    const float* A_log  = (const float*)d_in[7];
    const float* D_par  = (const float*)d_in[8];
    const float* W_out  = (const float*)d_in[9];
    const float* ln_g   = (const float*)d_in[10];
    const float* ln_b   = (const float*)d_in[11];
    float* out = (float*)d_out;

    k_ln  <<<ROWS, 256>>>(x, ln_g, ln_b);
    k_gemm_in <<<dim3((2*D_INNER)/128, ROWS/128), 256>>>(W_in);
    k_conv<<<(ROWS*D_INNER)/256, 256>>>(conv_w, conv_b);
    k_gemm_bc <<<dim3(1, ROWS/128), 256>>>(W_x);
    k_gemm_dt <<<dim3(D_INNER/128, ROWS/128), 256>>>(W_dt, b_dt);
    k_scan<<<(NB*D_INNER)/8, 256>>>(A_log, D_par);
    k_gemm_out<<<dim3(D_MODEL/128, ROWS/128), 256>>>(W_out, x, out);
}

// round 3
// speedup vs baseline: 1.1333x; 1.1333x over previous
#include <cuda_runtime.h>
#include <cuda_bf16.h>
#include <math.h>
#include <stdint.h>

#define D_MODEL 1024
#define D_INNER 2048
#define NT      1024
#define NB      2
#define ROWS    (NB*NT)
#define DSTATE  64

#define K_IN   1024
#define K3_IN  (3*K_IN)        // 3072
#define K_BIG  2048
#define K3_BIG (3*K_BIG)       // 6144
#define N_IN   (2*D_INNER)     // 4096
#define N_BCDT (128 + D_INNER) // 2176 = 17*128

// ---------------- device scratch ----------------
__device__ __align__(128) __nv_bfloat16 g_xnb [ROWS*K3_IN];
__device__ __align__(128) __nv_bfloat16 g_xcb [ROWS*K3_BIG];
__device__ __align__(128) __nv_bfloat16 g_ygb [ROWS*K3_BIG];
__device__ __align__(128) __nv_bfloat16 g_Wint [N_IN*K3_IN];
__device__ __align__(128) __nv_bfloat16 g_Wbcdt[N_BCDT*K3_BIG];
__device__ __align__(128) __nv_bfloat16 g_Woutt[D_MODEL*K3_BIG];
__device__ float g_xz[ROWS*2*D_INNER];
__device__ float g_xc[ROWS*D_INNER];
__device__ float g_bc[ROWS*2*DSTATE];
__device__ float g_dtm[ROWS];

// ---------------- PTX helpers ----------------
__device__ __forceinline__ uint32_t smem_u32(const void* p){
    uint32_t a; asm("{ .reg .u64 t; cvta.to.shared.u64 t, %1; cvt.u32.u64 %0, t; }" : "=r"(a) : "l"(p)); return a;
}
#define CP16(s,g)   asm volatile("cp.async.cg.shared.global [%0], [%1], 16;" :: "r"(s), "l"(g) : "memory")
#define CPCOMMIT()  asm volatile("cp.async.commit_group;" ::: "memory")
#define CPWAIT0()   asm volatile("cp.async.wait_group 0;" ::: "memory")
#define CPWAIT1()   asm volatile("cp.async.wait_group 1;" ::: "memory")

#define MMA16816(d,a,b) asm volatile( \
  "mma.sync.aligned.m16n8k16.row.col.f32.bf16.bf16.f32 " \
  "{%0,%1,%2,%3},{%4,%5,%6,%7},{%8,%9},{%0,%1,%2,%3};" \
  : "+f"((d)[0]),"+f"((d)[1]),"+f"((d)[2]),"+f"((d)[3]) \
  : "r"((a)[0]),"r"((a)[1]),"r"((a)[2]),"r"((a)[3]),"r"((b)[0]),"r"((b)[1]))

// ---------------- bf16x3 mma.sync GEMM body ----------------
// C[M,N] (fp32) = A'[M,K'] . B'[N,K']^T with per-MODE epilogue
// MODE 0: plain store  MODE 1: bx==0 -> store g_bc; bx>0 -> softplus rowsum
// MODE 2: store acc + aux (residual)
#define SROW 40   // padded smem row (bf16 elems): conflict-free (80B stride)
template<int MODE>
__device__ __forceinline__ void bgemm_body(const __nv_bfloat16* __restrict__ A,
                                           const __nv_bfloat16* __restrict__ Bm,
                                           int Kp, float* __restrict__ C, int ldc,
                                           const float* __restrict__ aux,
                                           float* __restrict__ rowsum)
{
    __shared__ __nv_bfloat16 As[2][128][SROW];
    __shared__ __nv_bfloat16 Bs[2][128][SROW];
    const int tid = threadIdx.x, lane = tid & 31, w = tid >> 5;
    const int wm = w >> 1, wn = w & 1, g = lane >> 2, tig = lane & 3;
    const int bx = blockIdx.x, by = blockIdx.y;

    const __nv_bfloat16* Ar = A  + (size_t)(by*128 + tid) * Kp;
    const __nv_bfloat16* Br = Bm + (size_t)(bx*128 + tid) * Kp;
    const uint32_t sA0 = smem_u32(&As[0][tid][0]);
    const uint32_t sB0 = smem_u32(&Bs[0][tid][0]);
    const uint32_t STG = 128*SROW*2;

    float acc[4][8][4];
    #pragma unroll
    for (int i=0;i<4;i++)
        #pragma unroll
        for (int j=0;j<8;j++)
            #pragma unroll
            for (int r=0;r<4;r++) acc[i][j][r] = 0.f;

    const int NC = Kp >> 5;   // k-tiles of 32
    // prologue: stage 0
    #pragma unroll
    for (int ch=0; ch<4; ch++){
        CP16(sA0 + ch*16, (const char*)(Ar) + ch*16);
        CP16(sB0 + ch*16, (const char*)(Br) + ch*16);
    }
    CPCOMMIT();

    for (int c = 0; c < NC; c++){
        if (c + 1 < NC){
            const uint32_t so = ((c+1) & 1) * STG;
            const char* ga = (const char*)(Ar + (c+1)*32);
            const char* gb = (const char*)(Br + (c+1)*32);
            #pragma unroll
            for (int ch=0; ch<4; ch++){
                CP16(sA0 + so + ch*16, ga + ch*16);
                CP16(sB0 + so + ch*16, gb + ch*16);
            }
            CPCOMMIT();
            CPWAIT1();
        } else {
            CPWAIT0();
        }
        __syncthreads();
        const int s = c & 1;
        #pragma unroll
        for (int kk = 0; kk < 32; kk += 16){
            uint32_t af[4][4], bf[8][2];
            #pragma unroll
            for (int mt=0; mt<4; mt++){
                const int r = wm*64 + mt*16;
                af[mt][0] = *(const uint32_t*)&As[s][r+g  ][kk + 2*tig];
                af[mt][1] = *(const uint32_t*)&As[s][r+g+8][kk + 2*tig];
                af[mt][2] = *(const uint32_t*)&As[s][r+g  ][kk + 2*tig + 8];
                af[mt][3] = *(const uint32_t*)&As[s][r+g+8][kk + 2*tig + 8];
            }
            #pragma unroll
            for (int nt=0; nt<8; nt++){
                const int r = wn*64 + nt*8 + g;
                bf[nt][0] = *(const uint32_t*)&Bs[s][r][kk + 2*tig];
                bf[nt][1] = *(const uint32_t*)&Bs[s][r][kk + 2*tig + 8];
            }
            #pragma unroll
            for (int mt=0; mt<4; mt++)
                #pragma unroll
                for (int nt=0; nt<8; nt++)
                    MMA16816(acc[mt][nt], af[mt], bf[nt]);
        }
        __syncthreads();
    }

    // -------- epilogue --------
    if (MODE == 1 && bx > 0){
        #pragma unroll
        for (int mt=0; mt<4; mt++){
            float s0 = 0.f, s1 = 0.f;
            #pragma unroll
            for (int nt=0; nt<8; nt++){
                const int col = (bx-1)*128 + wn*64 + nt*8 + 2*tig;
                const float a0 = aux[col], a1 = aux[col+1];
                float v;
                v = acc[mt][nt][0] + a0; v = (v>20.f)?v:log1pf(__expf(v)); s0 += v;
                v = acc[mt][nt][1] + a1; v = (v>20.f)?v:log1pf(__expf(v)); s0 += v;
                v = acc[mt][nt][2] + a0; v = (v>20.f)?v:log1pf(__expf(v)); s1 += v;
                v = acc[mt][nt][3] + a1; v = (v>20.f)?v:log1pf(__expf(v)); s1 += v;
            }
            s0 += __shfl_xor_sync(~0u, s0, 1); s0 += __shfl_xor_sync(~0u, s0, 2);
            s1 += __shfl_xor_sync(~0u, s1, 1); s1 += __shfl_xor_sync(~0u, s1, 2);
            if (tig == 0){
                const int r = by*128 + wm*64 + mt*16 + g;
                atomicAdd(&rowsum[r],     s0);
                atomicAdd(&rowsum[r + 8], s1);
            }
        }
    } else {
        const int colb = (MODE==1 ? 0 : bx*128) + wn*64 + 2*tig;
        const int ld   = (MODE==1 ? 128 : ldc);
        #pragma unroll
        for (int mt=0; mt<4; mt++){
            const int r0 = by*128 + wm*64 + mt*16 + g;
            #pragma unroll
            for (int nt=0; nt<8; nt++){
                const int col = colb + nt*8;
                float2 o0 = make_float2(acc[mt][nt][0], acc[mt][nt][1]);
                float2 o1 = make_float2(acc[mt][nt][2], acc[mt][nt][3]);
                if (MODE == 2){
                    float2 r0v = *(const float2*)(aux + (size_t)r0*ld + col);
                    float2 r1v = *(const float2*)(aux + (size_t)(r0+8)*ld + col);
                    o0.x += r0v.x; o0.y += r0v.y; o1.x += r1v.x; o1.y += r1v.y;
                }
                *(float2*)(C + (size_t)r0*ld + col)     = o0;
                *(float2*)(C + (size_t)(r0+8)*ld + col) = o1;
            }
        }
    }
}

__global__ __launch_bounds__(128) void k_bgemm_in(){
    bgemm_body<0>(g_xnb, g_Wint, K3_IN, g_xz, N_IN, nullptr, nullptr);
}
__global__ __launch_bounds__(128) void k_bgemm_bcdt(const float* __restrict__ bdt){
    bgemm_body<1>(g_xcb, g_Wbcdt, K3_BIG, g_bc, 128, bdt, g_dtm);
}
__global__ __launch_bounds__(128) void k_bgemm_out(const float* __restrict__ x, float* __restrict__ out){
    bgemm_body<2>(g_ygb, g_Woutt, K3_BIG, out, D_MODEL, x, nullptr);
}

// ---------------- weight transpose + hi/lo split ----------------
__device__ __forceinline__ void tr_body(const float* __restrict__ W, __nv_bfloat16* __restrict__ Bt,
                                        int K, int N, int rowoff, int ld3)
{
    __shared__ float t[32][33];
    const int tx = threadIdx.x & 31, ty = threadIdx.x >> 5;
    const int n0 = blockIdx.x*32, k0 = blockIdx.y*32;
    #pragma unroll
    for (int r=0;r<4;r++) t[ty + r*8][tx] = W[(size_t)(k0 + ty + r*8)*N + n0 + tx];
    __syncthreads();
    #pragma unroll
    for (int r=0;r<4;r++){
        const int n = n0 + ty + r*8, kk = k0 + tx;
        float v = t[tx][ty + r*8];
        __nv_bfloat16 hi = __float2bfloat16(v);
        __nv_bfloat16 lo = __float2bfloat16(v - __bfloat162float(hi));
        __nv_bfloat16* o = Bt + (size_t)(rowoff + n)*ld3;
        o[kk] = hi; o[K + kk] = lo; o[2*K + kk] = hi;
    }
}
__global__ __launch_bounds__(256) void k_tr_in (const float* W){ tr_body(W, g_Wint,  K_IN,  N_IN,    0,   K3_IN);  }
__global__ __launch_bounds__(256) void k_tr_x  (const float* W){ tr_body(W, g_Wbcdt, K_BIG, 128,     0,   K3_BIG); }
__global__ __launch_bounds__(256) void k_tr_dt (const float* W){ tr_body(W, g_Wbcdt, K_BIG, D_INNER, 128, K3_BIG); }
__global__ __launch_bounds__(256) void k_tr_out(const float* W){ tr_body(W, g_Woutt, K_BIG, D_MODEL, 0,   K3_BIG); }

// ---------------- layernorm -> bf16 A' (hi,hi,lo) ----------------
__global__ __launch_bounds__(256) void k_ln(const float* __restrict__ x,
                                            const float* __restrict__ g,
                                            const float* __restrict__ bb) {
    int row = blockIdx.x, tid = threadIdx.x;
    const float4 v = *(const float4*)(x + (size_t)row*D_MODEL + tid*4);
    float s = v.x+v.y+v.z+v.w;
    float q = v.x*v.x+v.y*v.y+v.z*v.z+v.w*v.w;
    #pragma unroll
    for (int o=16;o;o>>=1){ s += __shfl_xor_sync(~0u,s,o); q += __shfl_xor_sync(~0u,q,o); }
    __shared__ float ss[8], qq[8];
    int w = tid>>5;
    if ((tid&31)==0){ ss[w]=s; qq[w]=q; }
    __syncthreads();
    s=0.f; q=0.f;
    #pragma unroll
    for (int j=0;j<8;j++){ s+=ss[j]; q+=qq[j]; }
    float mu = s*(1.f/D_MODEL);
    float inv = rsqrtf(q*(1.f/D_MODEL) - mu*mu + 1e-5f);
    float4 gg = *(const float4*)(g + tid*4);
    float4 b4 = *(const float4*)(bb + tid*4);
    float o[4];
    o[0]=(v.x-mu)*inv*gg.x+b4.x; o[1]=(v.y-mu)*inv*gg.y+b4.y;
    o[2]=(v.z-mu)*inv*gg.z+b4.z; o[3]=(v.w-mu)*inv*gg.w+b4.w;
    __nv_bfloat16* dst = g_xnb + (size_t)row*K3_IN + tid*4;
    #pragma unroll
    for (int j=0;j<4;j++){
        __nv_bfloat16 hi = __float2bfloat16(o[j]);
        __nv_bfloat16 lo = __float2bfloat16(o[j] - __bfloat162float(hi));
        dst[j] = hi; dst[K_IN + j] = hi; dst[2*K_IN + j] = lo;
    }
}

// ---------------- conv(4) + silu ----------------
__global__ __launch_bounds__(256) void k_conv(const float* __restrict__ cw,
                                              const float* __restrict__ cb){
    int idx = blockIdx.x*256 + threadIdx.x;
    if (idx < ROWS) g_dtm[idx] = 0.f;
    int i = idx & (D_INNER-1);
    int row = idx >> 11;
    int t = row & (NT-1);
    int b = row >> 10;
    float4 w4 = *(const float4*)(cw + i*4);
    float ws[4] = {w4.x, w4.y, w4.z, w4.w};
    float acc = cb[i];
    const float* xp = g_xz + (size_t)(b*NT)*(2*D_INNER) + i;
    #pragma unroll
    for (int k=0;k<4;k++){
        int tt = t + k - 3;
        if (tt >= 0) acc += xp[(size_t)tt*(2*D_INNER)] * ws[k];
    }
    float sv = acc / (1.f + __expf(-acc));
    g_xc[idx] = sv;
    __nv_bfloat16 hi = __float2bfloat16(sv);
    __nv_bfloat16 lo = __float2bfloat16(sv - __bfloat162float(hi));
    __nv_bfloat16* dst = g_xcb + (size_t)row*K3_BIG + i;
    dst[0] = hi; dst[K_BIG] = hi; dst[2*K_BIG] = lo;
}

// ---------------- SSM scan ----------------
__global__ __launch_bounds__(256) void k_scan(const float* __restrict__ A_log,
                                              const float* __restrict__ Dp_){
    int wg = (blockIdx.x*blockDim.x + threadIdx.x) >> 5;
    int l  = threadIdx.x & 31;
    int b  = wg >> 11;
    int i  = wg & (D_INNER-1);
    float A0 = -__expf(A_log[i*DSTATE + 2*l]);
    float A1 = -__expf(A_log[i*DSTATE + 2*l + 1]);
    float Dp = Dp_[i];
    float h0 = 0.f, h1 = 0.f;
    const size_t base = (size_t)b*NT;
    const float* bcb = g_bc + base*(2*DSTATE);
    for (int t=0; t<NT; t++){
        float dtm = g_dtm[base + t] * (1.f/(float)D_INNER);
        float xc  = g_xc[(base+t)*D_INNER + i];
        float2 Bv = *(const float2*)(bcb + (size_t)t*(2*DSTATE) + 2*l);
        float2 Cv = *(const float2*)(bcb + (size_t)t*(2*DSTATE) + DSTATE + 2*l);
        float xdt = xc * dtm;
        h0 = __expf(dtm*A0)*h0 + xdt*Bv.x;
        h1 = __expf(dtm*A1)*h1 + xdt*Bv.y;
        float yp = h0*Cv.x + h1*Cv.y;
        #pragma unroll
        for (int o=16;o;o>>=1) yp += __shfl_xor_sync(~0u, yp, o);
        if (l == 0){
            float z  = g_xz[(base+t)*(2*D_INNER) + D_INNER + i];
            float sz = z / (1.f + __expf(-z));
            float y  = (yp + Dp*xc) * sz;
            __nv_bfloat16 hi = __float2bfloat16(y);
            __nv_bfloat16 lo = __float2bfloat16(y - __bfloat162float(hi));
            __nv_bfloat16* dst = g_ygb + (base+t)*K3_BIG + i;
            dst[0] = hi; dst[K_BIG] = hi; dst[2*K_BIG] = lo;
        }
    }
}

// ---------------- launch ----------------
extern "C" void kernel_launch(void* const* d_in, const int* in_sizes, int n_in,
                              void* d_out, int out_size) {
    const float* x      = (const float*)d_in[0];
    const float* W_in   = (const float*)d_in[1];
    const float* conv_w = (const float*)d_in[2];
    const float* conv_b = (const float*)d_in[3];
    const float* W_x    = (const float*)d_in[4];
    const float* W_dt   = (const float*)d_in[5];
    const float* b_dt   = (const float*)d_in[6];
    const float* A_log  = (const float*)d_in[7];
    const float* D_par  = (const float*)d_in[8];
    const float* W_out  = (const float*)d_in[9];
    const float* ln_g   = (const float*)d_in[10];
    const float* ln_b   = (const float*)d_in[11];
    float* out = (float*)d_out;

    k_tr_in <<<dim3(N_IN/32,    K_IN/32),  256>>>(W_in);
    k_tr_x  <<<dim3(128/32,     K_BIG/32), 256>>>(W_x);
    k_tr_dt <<<dim3(D_INNER/32, K_BIG/32), 256>>>(W_dt);
    k_tr_out<<<dim3(D_MODEL/32, K_BIG/32), 256>>>(W_out);

    k_ln<<<ROWS, 256>>>(x, ln_g, ln_b);
    k_bgemm_in<<<dim3(N_IN/128, ROWS/128), 128>>>();
    k_conv<<<(ROWS*D_INNER)/256, 256>>>(conv_w, conv_b);
    k_bgemm_bcdt<<<dim3(N_BCDT/128, ROWS/128), 128>>>(b_dt);
    k_scan<<<(NB*D_INNER)/8, 256>>>(A_log, D_par);
    k_bgemm_out<<<dim3(D_MODEL/128, ROWS/128), 128>>>(x, out);
}

// round 4
// speedup vs baseline: 2.0453x; 1.8048x over previous
#include <cuda_runtime.h>
#include <cuda_fp16.h>
#include <math.h>
#include <stdint.h>

#define D_MODEL 1024
#define D_INNER 2048
#define NT      1024
#define NB      2
#define ROWS    (NB*NT)
#define DSTATE  64

#define K_IN   1024
#define K_BIG  2048
#define N_IN   (2*D_INNER)     // 4096
#define N_BCDT (128 + D_INNER) // 2176 = 17*128

// ---------------- device scratch ----------------
__device__ __align__(128) __half g_xnh [ROWS*K_IN];      // ln output (A of gemm_in)
__device__ __align__(128) __half g_xch [ROWS*K_BIG];     // conv+silu (A of bcdt gemm)
__device__ __align__(128) __half g_ygh [ROWS*K_BIG];     // gated y  (A of out gemm)
__device__ __align__(128) __half g_Winh [N_IN*K_IN];     // W_in^T
__device__ __align__(128) __half g_Wbcdth[N_BCDT*K_BIG]; // [W_x|W_dt]^T
__device__ __align__(128) __half g_Wouth[D_MODEL*K_BIG]; // W_out^T
__device__ float g_xz[ROWS*2*D_INNER];   // fp32 xz (xp|z)
__device__ float g_xc[ROWS*D_INNER];     // fp32 conv+silu (scan)
__device__ float g_bc[ROWS*2*DSTATE];
__device__ float g_dtm[ROWS];

// ---------------- PTX helpers ----------------
__device__ __forceinline__ uint32_t smem_u32(const void* p){
    uint32_t a; asm("{ .reg .u64 t; cvta.to.shared.u64 t, %1; cvt.u32.u64 %0, t; }" : "=r"(a) : "l"(p)); return a;
}
#define CP16(s,g)   asm volatile("cp.async.cg.shared.global [%0], [%1], 16;" :: "r"(s), "l"(g) : "memory")
#define CPCOMMIT()  asm volatile("cp.async.commit_group;" ::: "memory")
#define CPWAIT0()   asm volatile("cp.async.wait_group 0;" ::: "memory")
#define CPWAIT1()   asm volatile("cp.async.wait_group 1;" ::: "memory")

#define MMA16816(d,a,b) asm volatile( \
  "mma.sync.aligned.m16n8k16.row.col.f32.f16.f16.f32 " \
  "{%0,%1,%2,%3},{%4,%5,%6,%7},{%8,%9},{%0,%1,%2,%3};" \
  : "+f"((d)[0]),"+f"((d)[1]),"+f"((d)[2]),"+f"((d)[3]) \
  : "r"((a)[0]),"r"((a)[1]),"r"((a)[2]),"r"((a)[3]),"r"((b)[0]),"r"((b)[1]))

// ---------------- fp16 mma.sync GEMM ----------------
// C[M,N] (fp32) = A[M,K] . B[N,K]^T
// MODE 0: plain store  MODE 1: bx==0 -> store g_bc; bx>0 -> softplus rowsum
// MODE 2: store acc + aux (residual)
#define SROW 40   // padded smem row (half elems): 80B stride, conflict-free
template<int MODE>
__device__ __forceinline__ void bgemm_body(const __half* __restrict__ A,
                                           const __half* __restrict__ Bm,
                                           int Kp, float* __restrict__ C, int ldc,
                                           const float* __restrict__ aux,
                                           float* __restrict__ rowsum)
{
    __shared__ __half As[2][128][SROW];
    __shared__ __half Bs[2][128][SROW];
    const int tid = threadIdx.x, lane = tid & 31, w = tid >> 5;
    const int wm = w >> 1, wn = w & 1, g = lane >> 2, tig = lane & 3;
    const int bx = blockIdx.x, by = blockIdx.y;

    // load mapping: row = tid>>1, two 16B chunks at byte offset (tid&1)*32 + j*16
    const int lrow = tid >> 1, lhalf = tid & 1;
    const __half* Ag = A  + (size_t)(by*128 + lrow) * Kp + lhalf*16;
    const __half* Bg = Bm + (size_t)(bx*128 + lrow) * Kp + lhalf*16;
    const uint32_t sA = smem_u32(&As[0][lrow][0]) + lhalf*32;
    const uint32_t sB = smem_u32(&Bs[0][lrow][0]) + lhalf*32;
    const uint32_t STG = 128*SROW*2;

    float acc[2][8][4];
    #pragma unroll
    for (int i=0;i<2;i++)
        #pragma unroll
        for (int j=0;j<8;j++)
            #pragma unroll
            for (int r=0;r<4;r++) acc[i][j][r] = 0.f;

    const int NC = Kp >> 5;
    CP16(sA,      (const char*)Ag);
    CP16(sA + 16, (const char*)Ag + 16);
    CP16(sB,      (const char*)Bg);
    CP16(sB + 16, (const char*)Bg + 16);
    CPCOMMIT();

    for (int c = 0; c < NC; c++){
        if (c + 1 < NC){
            const uint32_t so = ((c+1) & 1) * STG;
            const char* ga = (const char*)(Ag + (c+1)*32);
            const char* gb = (const char*)(Bg + (c+1)*32);
            CP16(sA + so,      ga);
            CP16(sA + so + 16, ga + 16);
            CP16(sB + so,      gb);
            CP16(sB + so + 16, gb + 16);
            CPCOMMIT();
            CPWAIT1();
        } else {
            CPWAIT0();
        }
        __syncthreads();
        const int s = c & 1;
        #pragma unroll
        for (int kk = 0; kk < 32; kk += 16){
            uint32_t af[2][4], bf[8][2];
            #pragma unroll
            for (int mt=0; mt<2; mt++){
                const int r = wm*32 + mt*16;
                af[mt][0] = *(const uint32_t*)&As[s][r+g  ][kk + 2*tig];
                af[mt][1] = *(const uint32_t*)&As[s][r+g+8][kk + 2*tig];
                af[mt][2] = *(const uint32_t*)&As[s][r+g  ][kk + 2*tig + 8];
                af[mt][3] = *(const uint32_t*)&As[s][r+g+8][kk + 2*tig + 8];
            }
            #pragma unroll
            for (int nt=0; nt<8; nt++){
                const int r = wn*64 + nt*8 + g;
                bf[nt][0] = *(const uint32_t*)&Bs[s][r][kk + 2*tig];
                bf[nt][1] = *(const uint32_t*)&Bs[s][r][kk + 2*tig + 8];
            }
            #pragma unroll
            for (int mt=0; mt<2; mt++)
                #pragma unroll
                for (int nt=0; nt<8; nt++)
                    MMA16816(acc[mt][nt], af[mt], bf[nt]);
        }
        __syncthreads();
    }

    // -------- epilogue --------
    if (MODE == 1 && bx > 0){
        #pragma unroll
        for (int mt=0; mt<2; mt++){
            float s0 = 0.f, s1 = 0.f;
            #pragma unroll
            for (int nt=0; nt<8; nt++){
                const int col = (bx-1)*128 + wn*64 + nt*8 + 2*tig;
                const float a0 = aux[col], a1 = aux[col+1];
                float v;
                v = acc[mt][nt][0] + a0; v = (v>20.f)?v:log1pf(__expf(v)); s0 += v;
                v = acc[mt][nt][1] + a1; v = (v>20.f)?v:log1pf(__expf(v)); s0 += v;
                v = acc[mt][nt][2] + a0; v = (v>20.f)?v:log1pf(__expf(v)); s1 += v;
                v = acc[mt][nt][3] + a1; v = (v>20.f)?v:log1pf(__expf(v)); s1 += v;
            }
            s0 += __shfl_xor_sync(~0u, s0, 1); s0 += __shfl_xor_sync(~0u, s0, 2);
            s1 += __shfl_xor_sync(~0u, s1, 1); s1 += __shfl_xor_sync(~0u, s1, 2);
            if (tig == 0){
                const int r = by*128 + wm*32 + mt*16 + g;
                atomicAdd(&rowsum[r],     s0);
                atomicAdd(&rowsum[r + 8], s1);
            }
        }
    } else {
        const int colb = (MODE==1 ? 0 : bx*128) + wn*64 + 2*tig;
        const int ld   = (MODE==1 ? 128 : ldc);
        #pragma unroll
        for (int mt=0; mt<2; mt++){
            const int r0 = by*128 + wm*32 + mt*16 + g;
            #pragma unroll
            for (int nt=0; nt<8; nt++){
                const int col = colb + nt*8;
                float2 o0 = make_float2(acc[mt][nt][0], acc[mt][nt][1]);
                float2 o1 = make_float2(acc[mt][nt][2], acc[mt][nt][3]);
                if (MODE == 2){
                    float2 r0v = *(const float2*)(aux + (size_t)r0*ld + col);
                    float2 r1v = *(const float2*)(aux + (size_t)(r0+8)*ld + col);
                    o0.x += r0v.x; o0.y += r0v.y; o1.x += r1v.x; o1.y += r1v.y;
                }
                *(float2*)(C + (size_t)r0*ld + col)     = o0;
                *(float2*)(C + (size_t)(r0+8)*ld + col) = o1;
            }
        }
    }
}

__global__ __launch_bounds__(256,2) void k_bgemm_in(){
    bgemm_body<0>(g_xnh, g_Winh, K_IN, g_xz, N_IN, nullptr, nullptr);
}
__global__ __launch_bounds__(256,2) void k_bgemm_bcdt(const float* __restrict__ bdt){
    bgemm_body<1>(g_xch, g_Wbcdth, K_BIG, g_bc, 128, bdt, g_dtm);
}
__global__ __launch_bounds__(256,2) void k_bgemm_out(const float* __restrict__ x, float* __restrict__ out){
    bgemm_body<2>(g_ygh, g_Wouth, K_BIG, out, D_MODEL, x, nullptr);
}

// ---------------- weight transpose -> fp16 ----------------
__device__ __forceinline__ void tr_body(const float* __restrict__ W, __half* __restrict__ Bt,
                                        int K, int N, int rowoff, int ldk)
{
    __shared__ float t[32][33];
    const int tx = threadIdx.x & 31, ty = threadIdx.x >> 5;
    const int n0 = blockIdx.x*32, k0 = blockIdx.y*32;
    #pragma unroll
    for (int r=0;r<4;r++) t[ty + r*8][tx] = W[(size_t)(k0 + ty + r*8)*N + n0 + tx];
    __syncthreads();
    #pragma unroll
    for (int r=0;r<4;r++){
        const int n = n0 + ty + r*8, kk = k0 + tx;
        Bt[(size_t)(rowoff + n)*ldk + kk] = __float2half(t[tx][ty + r*8]);
    }
}
__global__ __launch_bounds__(256) void k_tr_in (const float* W){ tr_body(W, g_Winh,   K_IN,  N_IN,    0,   K_IN);  }
__global__ __launch_bounds__(256) void k_tr_x  (const float* W){ tr_body(W, g_Wbcdth, K_BIG, 128,     0,   K_BIG); }
__global__ __launch_bounds__(256) void k_tr_dt (const float* W){ tr_body(W, g_Wbcdth, K_BIG, D_INNER, 128, K_BIG); }
__global__ __launch_bounds__(256) void k_tr_out(const float* W){ tr_body(W, g_Wouth,  K_BIG, D_MODEL, 0,   K_BIG); }

// ---------------- layernorm -> fp16 ----------------
__global__ __launch_bounds__(256) void k_ln(const float* __restrict__ x,
                                            const float* __restrict__ g,
                                            const float* __restrict__ bb) {
    int row = blockIdx.x, tid = threadIdx.x;
    const float4 v = *(const float4*)(x + (size_t)row*D_MODEL + tid*4);
    float s = v.x+v.y+v.z+v.w;
    float q = v.x*v.x+v.y*v.y+v.z*v.z+v.w*v.w;
    #pragma unroll
    for (int o=16;o;o>>=1){ s += __shfl_xor_sync(~0u,s,o); q += __shfl_xor_sync(~0u,q,o); }
    __shared__ float ss[8], qq[8];
    int w = tid>>5;
    if ((tid&31)==0){ ss[w]=s; qq[w]=q; }
    __syncthreads();
    s=0.f; q=0.f;
    #pragma unroll
    for (int j=0;j<8;j++){ s+=ss[j]; q+=qq[j]; }
    float mu = s*(1.f/D_MODEL);
    float inv = rsqrtf(q*(1.f/D_MODEL) - mu*mu + 1e-5f);
    float4 gg = *(const float4*)(g + tid*4);
    float4 b4 = *(const float4*)(bb + tid*4);
    __half2 h0 = __floats2half2_rn((v.x-mu)*inv*gg.x+b4.x, (v.y-mu)*inv*gg.y+b4.y);
    __half2 h1 = __floats2half2_rn((v.z-mu)*inv*gg.z+b4.z, (v.w-mu)*inv*gg.w+b4.w);
    *(__half2*)(g_xnh + (size_t)row*K_IN + tid*4)     = h0;
    *(__half2*)(g_xnh + (size_t)row*K_IN + tid*4 + 2) = h1;
}

// ---------------- conv(4) + silu ----------------
__global__ __launch_bounds__(256) void k_conv(const float* __restrict__ cw,
                                              const float* __restrict__ cb){
    int idx = blockIdx.x*256 + threadIdx.x;
    if (idx < ROWS) g_dtm[idx] = 0.f;
    int i = idx & (D_INNER-1);
    int row = idx >> 11;
    int t = row & (NT-1);
    int b = row >> 10;
    float4 w4 = *(const float4*)(cw + i*4);
    float ws[4] = {w4.x, w4.y, w4.z, w4.w};
    float acc = cb[i];
    const float* xp = g_xz + (size_t)(b*NT)*(2*D_INNER) + i;
    #pragma unroll
    for (int k=0;k<4;k++){
        int tt = t + k - 3;
        if (tt >= 0) acc += xp[(size_t)tt*(2*D_INNER)] * ws[k];
    }
    float sv = acc / (1.f + __expf(-acc));
    g_xc[idx] = sv;
    g_xch[(size_t)row*K_BIG + i] = __float2half(sv);
}

// ---------------- SSM scan ----------------
__global__ __launch_bounds__(256) void k_scan(const float* __restrict__ A_log,
                                              const float* __restrict__ Dp_){
    int wg = (blockIdx.x*blockDim.x + threadIdx.x) >> 5;
    int l  = threadIdx.x & 31;
    int b  = wg >> 11;
    int i  = wg & (D_INNER-1);
    float A0 = -__expf(A_log[i*DSTATE + 2*l]);
    float A1 = -__expf(A_log[i*DSTATE + 2*l + 1]);
    float Dp = Dp_[i];
    float h0 = 0.f, h1 = 0.f;
    const size_t base = (size_t)b*NT;
    const float* bcb = g_bc + base*(2*DSTATE);
    for (int t=0; t<NT; t++){
        float dtm = g_dtm[base + t] * (1.f/(float)D_INNER);
        float xc  = g_xc[(base+t)*D_INNER + i];
        float2 Bv = *(const float2*)(bcb + (size_t)t*(2*DSTATE) + 2*l);
        float2 Cv = *(const float2*)(bcb + (size_t)t*(2*DSTATE) + DSTATE + 2*l);
        float xdt = xc * dtm;
        h0 = __expf(dtm*A0)*h0 + xdt*Bv.x;
        h1 = __expf(dtm*A1)*h1 + xdt*Bv.y;
        float yp = h0*Cv.x + h1*Cv.y;
        #pragma unroll
        for (int o=16;o;o>>=1) yp += __shfl_xor_sync(~0u, yp, o);
        if (l == 0){
            float z  = g_xz[(base+t)*(2*D_INNER) + D_INNER + i];
            float sz = z / (1.f + __expf(-z));
            g_ygh[(base+t)*K_BIG + i] = __float2half((yp + Dp*xc) * sz);
        }
    }
}

// ---------------- launch ----------------
extern "C" void kernel_launch(void* const* d_in, const int* in_sizes, int n_in,
                              void* d_out, int out_size) {
    const float* x      = (const float*)d_in[0];
    const float* W_in   = (const float*)d_in[1];
    const float* conv_w = (const float*)d_in[2];
    const float* conv_b = (const float*)d_in[3];
    const float* W_x    = (const float*)d_in[4];
    const float* W_dt   = (const float*)d_in[5];
    const float* b_dt   = (const float*)d_in[6];
    const float* A_log  = (const float*)d_in[7];
    const float* D_par  = (const float*)d_in[8];
    const float* W_out  = (const float*)d_in[9];
    const float* ln_g   = (const float*)d_in[10];
    const float* ln_b   = (const float*)d_in[11];
    float* out = (float*)d_out;

    k_tr_in <<<dim3(N_IN/32,    K_IN/32),  256>>>(W_in);
    k_tr_x  <<<dim3(128/32,     K_BIG/32), 256>>>(W_x);
    k_tr_dt <<<dim3(D_INNER/32, K_BIG/32), 256>>>(W_dt);
    k_tr_out<<<dim3(D_MODEL/32, K_BIG/32), 256>>>(W_out);

    k_ln<<<ROWS, 256>>>(x, ln_g, ln_b);
    k_bgemm_in<<<dim3(N_IN/128, ROWS/128), 256>>>();
    k_conv<<<(ROWS*D_INNER)/256, 256>>>(conv_w, conv_b);
    k_bgemm_bcdt<<<dim3(N_BCDT/128, ROWS/128), 256>>>(b_dt);
    k_scan<<<(NB*D_INNER)/8, 256>>>(A_log, D_par);
    k_bgemm_out<<<dim3(D_MODEL/128, ROWS/128), 256>>>(x, out);
}

// round 7
// speedup vs baseline: 2.1172x; 1.0352x over previous
#include <cuda_runtime.h>
#include <cuda_fp16.h>
#include <math.h>
#include <stdint.h>

#define D_MODEL 1024
#define D_INNER 2048
#define NT      1024
#define NB      2
#define ROWS    (NB*NT)
#define DSTATE  64

#define K_IN   1024
#define K_BIG  2048
#define N_IN   (2*D_INNER)     // 4096
#define N_BCDT (128 + D_INNER) // 2176 = 17*128

// ---------------- device scratch ----------------
__device__ __align__(128) __half g_xnh [ROWS*K_IN];
__device__ __align__(128) __half g_xch [ROWS*K_BIG];
__device__ __align__(128) __half g_ygh [ROWS*K_BIG];
__device__ __align__(128) __half g_Winh [N_IN*K_IN];
__device__ __align__(128) __half g_Wbcdth[N_BCDT*K_BIG];
__device__ __align__(128) __half g_Wouth[D_MODEL*K_BIG];
__device__ float g_xz[ROWS*2*D_INNER];
__device__ float g_xc[ROWS*D_INNER];
__device__ float g_bc[ROWS*2*DSTATE];
__device__ float g_dtm[ROWS];

// ---------------- PTX helpers ----------------
__device__ __forceinline__ uint32_t smem_u32(const void* p){
    uint32_t a; asm("{ .reg .u64 t; cvta.to.shared.u64 t, %1; cvt.u32.u64 %0, t; }" : "=r"(a) : "l"(p)); return a;
}
#define CP16(s,g)   asm volatile("cp.async.cg.shared.global [%0], [%1], 16;" :: "r"(s), "l"(g) : "memory")
#define CPCOMMIT()  asm volatile("cp.async.commit_group;" ::: "memory")
#define CPWAIT0()   asm volatile("cp.async.wait_group 0;" ::: "memory")
#define CPWAIT1()   asm volatile("cp.async.wait_group 1;" ::: "memory")

#define MMA16816(d,a,b) asm volatile( \
  "mma.sync.aligned.m16n8k16.row.col.f32.f16.f16.f32 " \
  "{%0,%1,%2,%3},{%4,%5,%6,%7},{%8,%9},{%0,%1,%2,%3};" \
  : "+f"((d)[0]),"+f"((d)[1]),"+f"((d)[2]),"+f"((d)[3]) \
  : "r"((a)[0]),"r"((a)[1]),"r"((a)[2]),"r"((a)[3]),"r"((b)[0]),"r"((b)[1]))

#define SROW 40   // padded smem row (halves): 80B stride, conflict-free fragment loads

// ---------------- fp16 mma.sync GEMM: CTA 128x128, 4 warps, warp 64x64 ----------------
// C[M,N](fp32) = A[M,K].B[N,K]^T
// MODE 0: plain store   MODE 1: bx==0 -> store g_bc(ldc=128); bx>0 -> softplus rowsum
// MODE 2: store acc + aux (residual)
template<int MODE>
__device__ __forceinline__ void gbody(const __half* __restrict__ A,
                                      const __half* __restrict__ Bm,
                                      int Kp, float* __restrict__ C, int ldc,
                                      const float* __restrict__ aux,
                                      float* __restrict__ rowsum)
{
    __shared__ __half As[2][128][SROW];   // 20 KB
    __shared__ __half Bs[2][128][SROW];   // 20 KB  (40 KB static total)
    const int tid = threadIdx.x, lane = tid & 31, w = tid >> 5;
    const int wm = w >> 1, wn = w & 1;          // 2x2 warp grid, warp tile 64x64
    const int g = lane >> 2, tig = lane & 3;
    const int bx = blockIdx.x, by = blockIdx.y;
    const uint32_t STG = 128*SROW*2;            // bytes per stage

    // per-thread load map: 4 chunks of 16B for A, 4 for B (covers 128 rows x 32 halves)
    uint32_t aAd[4], bAd[4];
    const __half* aG[4];
    const __half* bG[4];
    #pragma unroll
    for (int i=0;i<4;i++){
        const int c = tid + i*128, row = c >> 2, off = (c & 3) * 8;
        aAd[i] = smem_u32(&As[0][row][off]);
        bAd[i] = smem_u32(&Bs[0][row][off]);
        aG[i]  = A  + (size_t)(by*128 + row)*Kp + off;
        bG[i]  = Bm + (size_t)(bx*128 + row)*Kp + off;
    }

    float acc[4][8][4];
    #pragma unroll
    for (int i=0;i<4;i++)
        #pragma unroll
        for (int j=0;j<8;j++)
            #pragma unroll
            for (int r=0;r<4;r++) acc[i][j][r] = 0.f;

    const int NC = Kp >> 5;
    // prologue: stage 0
    #pragma unroll
    for (int i=0;i<4;i++){ CP16(aAd[i], aG[i]); CP16(bAd[i], bG[i]); }
    CPCOMMIT();

    for (int c=0; c<NC; c++){
        if (c + 1 < NC){
            const uint32_t so = ((c+1) & 1) * STG;
            #pragma unroll
            for (int i=0;i<4;i++){
                CP16(aAd[i] + so, aG[i] + (size_t)(c+1)*32);
                CP16(bAd[i] + so, bG[i] + (size_t)(c+1)*32);
            }
            CPCOMMIT();
            CPWAIT1();
        } else {
            CPWAIT0();
        }
        __syncthreads();
        const int s = c & 1;
        #pragma unroll
        for (int kk=0; kk<32; kk+=16){
            uint32_t af[4][4], bf[8][2];
            #pragma unroll
            for (int mt=0; mt<4; mt++){
                const int r = wm*64 + mt*16;
                af[mt][0] = *(const uint32_t*)&As[s][r+g  ][kk + 2*tig];
                af[mt][1] = *(const uint32_t*)&As[s][r+g+8][kk + 2*tig];
                af[mt][2] = *(const uint32_t*)&As[s][r+g  ][kk + 2*tig + 8];
                af[mt][3] = *(const uint32_t*)&As[s][r+g+8][kk + 2*tig + 8];
            }
            #pragma unroll
            for (int nt=0; nt<8; nt++){
                const int r = wn*64 + nt*8 + g;
                bf[nt][0] = *(const uint32_t*)&Bs[s][r][kk + 2*tig];
                bf[nt][1] = *(const uint32_t*)&Bs[s][r][kk + 2*tig + 8];
            }
            #pragma unroll
            for (int mt=0; mt<4; mt++)
                #pragma unroll
                for (int nt=0; nt<8; nt++)
                    MMA16816(acc[mt][nt], af[mt], bf[nt]);
        }
        __syncthreads();   // all reads of stage s done before anyone overwrites it next iter
    }

    // -------- epilogue --------
    if (MODE == 1 && bx > 0){
        #pragma unroll
        for (int mt=0; mt<4; mt++){
            float s0 = 0.f, s1 = 0.f;
            #pragma unroll
            for (int nt=0; nt<8; nt++){
                const int col = (bx-1)*128 + wn*64 + nt*8 + 2*tig;
                const float a0 = aux[col], a1 = aux[col+1];
                float v;
                v = acc[mt][nt][0] + a0; v = (v>20.f)?v:log1pf(__expf(v)); s0 += v;
                v = acc[mt][nt][1] + a1; v = (v>20.f)?v:log1pf(__expf(v)); s0 += v;
                v = acc[mt][nt][2] + a0; v = (v>20.f)?v:log1pf(__expf(v)); s1 += v;
                v = acc[mt][nt][3] + a1; v = (v>20.f)?v:log1pf(__expf(v)); s1 += v;
            }
            s0 += __shfl_xor_sync(~0u, s0, 1); s0 += __shfl_xor_sync(~0u, s0, 2);
            s1 += __shfl_xor_sync(~0u, s1, 1); s1 += __shfl_xor_sync(~0u, s1, 2);
            if (tig == 0){
                const int r = by*128 + wm*64 + mt*16 + g;
                atomicAdd(&rowsum[r],     s0);
                atomicAdd(&rowsum[r + 8], s1);
            }
        }
    } else {
        const int colb = (MODE==1 ? 0 : bx*128) + wn*64 + 2*tig;
        const int ld   = (MODE==1 ? 128 : ldc);
        #pragma unroll
        for (int mt=0; mt<4; mt++){
            const int r0 = by*128 + wm*64 + mt*16 + g;
            #pragma unroll
            for (int nt=0; nt<8; nt++){
                const int col = colb + nt*8;
                float2 o0 = make_float2(acc[mt][nt][0], acc[mt][nt][1]);
                float2 o1 = make_float2(acc[mt][nt][2], acc[mt][nt][3]);
                if (MODE == 2){
                    float2 r0v = *(const float2*)(aux + (size_t)r0*ld + col);
                    float2 r1v = *(const float2*)(aux + (size_t)(r0+8)*ld + col);
                    o0.x += r0v.x; o0.y += r0v.y; o1.x += r1v.x; o1.y += r1v.y;
                }
                *(float2*)(C + (size_t)r0*ld + col)     = o0;
                *(float2*)(C + (size_t)(r0+8)*ld + col) = o1;
            }
        }
    }
}

__global__ __launch_bounds__(128,2) void k_bgemm_in(){
    gbody<0>(g_xnh, g_Winh, K_IN, g_xz, N_IN, nullptr, nullptr);
}
__global__ __launch_bounds__(128,2) void k_bgemm_bcdt(const float* __restrict__ bdt){
    gbody<1>(g_xch, g_Wbcdth, K_BIG, g_bc, 128, bdt, g_dtm);
}
__global__ __launch_bounds__(128,2) void k_bgemm_out(const float* __restrict__ x, float* __restrict__ out){
    gbody<2>(g_ygh, g_Wouth, K_BIG, out, D_MODEL, x, nullptr);
}

// ---------------- weight transpose -> fp16 ----------------
__device__ __forceinline__ void tr_body(const float* __restrict__ W, __half* __restrict__ Bt,
                                        int K, int N, int rowoff, int ldk)
{
    __shared__ float t[32][33];
    const int tx = threadIdx.x & 31, ty = threadIdx.x >> 5;
    const int n0 = blockIdx.x*32, k0 = blockIdx.y*32;
    #pragma unroll
    for (int r=0;r<4;r++) t[ty + r*8][tx] = W[(size_t)(k0 + ty + r*8)*N + n0 + tx];
    __syncthreads();
    #pragma unroll
    for (int r=0;r<4;r++){
        const int n = n0 + ty + r*8, kk = k0 + tx;
        Bt[(size_t)(rowoff + n)*ldk + kk] = __float2half(t[tx][ty + r*8]);
    }
}
__global__ __launch_bounds__(256) void k_tr_in (const float* W){ tr_body(W, g_Winh,   K_IN,  N_IN,    0,   K_IN);  }
__global__ __launch_bounds__(256) void k_tr_x  (const float* W){ tr_body(W, g_Wbcdth, K_BIG, 128,     0,   K_BIG); }
__global__ __launch_bounds__(256) void k_tr_dt (const float* W){ tr_body(W, g_Wbcdth, K_BIG, D_INNER, 128, K_BIG); }
__global__ __launch_bounds__(256) void k_tr_out(const float* W){ tr_body(W, g_Wouth,  K_BIG, D_MODEL, 0,   K_BIG); }

// ---------------- layernorm -> fp16 ----------------
__global__ __launch_bounds__(256) void k_ln(const float* __restrict__ x,
                                            const float* __restrict__ g,
                                            const float* __restrict__ bb) {
    int row = blockIdx.x, tid = threadIdx.x;
    const float4 v = *(const float4*)(x + (size_t)row*D_MODEL + tid*4);
    float s = v.x+v.y+v.z+v.w;
    float q = v.x*v.x+v.y*v.y+v.z*v.z+v.w*v.w;
    #pragma unroll
    for (int o=16;o;o>>=1){ s += __shfl_xor_sync(~0u,s,o); q += __shfl_xor_sync(~0u,q,o); }
    __shared__ float ss[8], qq[8];
    int w = tid>>5;
    if ((tid&31)==0){ ss[w]=s; qq[w]=q; }
    __syncthreads();
    s=0.f; q=0.f;
    #pragma unroll
    for (int j=0;j<8;j++){ s+=ss[j]; q+=qq[j]; }
    float mu = s*(1.f/D_MODEL);
    float inv = rsqrtf(q*(1.f/D_MODEL) - mu*mu + 1e-5f);
    float4 gg = *(const float4*)(g + tid*4);
    float4 b4 = *(const float4*)(bb + tid*4);
    __half2 h0 = __floats2half2_rn((v.x-mu)*inv*gg.x+b4.x, (v.y-mu)*inv*gg.y+b4.y);
    __half2 h1 = __floats2half2_rn((v.z-mu)*inv*gg.z+b4.z, (v.w-mu)*inv*gg.w+b4.w);
    *(__half2*)(g_xnh + (size_t)row*K_IN + tid*4)     = h0;
    *(__half2*)(g_xnh + (size_t)row*K_IN + tid*4 + 2) = h1;
}

// ---------------- conv(4) + silu ----------------
__global__ __launch_bounds__(256) void k_conv(const float* __restrict__ cw,
                                              const float* __restrict__ cb){
    int idx = blockIdx.x*256 + threadIdx.x;
    if (idx < ROWS) g_dtm[idx] = 0.f;
    int i = idx & (D_INNER-1);
    int row = idx >> 11;
    int t = row & (NT-1);
    int b = row >> 10;
    float4 w4 = *(const float4*)(cw + i*4);
    float ws[4] = {w4.x, w4.y, w4.z, w4.w};
    float acc = cb[i];
    const float* xp = g_xz + (size_t)(b*NT)*(2*D_INNER) + i;
    #pragma unroll
    for (int k=0;k<4;k++){
        int tt = t + k - 3;
        if (tt >= 0) acc += xp[(size_t)tt*(2*D_INNER)] * ws[k];
    }
    float sv = acc / (1.f + __expf(-acc));
    g_xc[idx] = sv;
    g_xch[(size_t)row*K_BIG + i] = __float2half(sv);
}

// ---------------- SSM scan ----------------
__global__ __launch_bounds__(256) void k_scan(const float* __restrict__ A_log,
                                              const float* __restrict__ Dp_){
    int wg = (blockIdx.x*blockDim.x + threadIdx.x) >> 5;
    int l  = threadIdx.x & 31;
    int b  = wg >> 11;
    int i  = wg & (D_INNER-1);
    float A0 = -__expf(A_log[i*DSTATE + 2*l]);
    float A1 = -__expf(A_log[i*DSTATE + 2*l + 1]);
    float Dp = Dp_[i];
    float h0 = 0.f, h1 = 0.f;
    const size_t base = (size_t)b*NT;
    const float* bcb = g_bc + base*(2*DSTATE);
    for (int t=0; t<NT; t++){
        float dtm = g_dtm[base + t] * (1.f/(float)D_INNER);
        float xc  = g_xc[(base+t)*D_INNER + i];
        float2 Bv = *(const float2*)(bcb + (size_t)t*(2*DSTATE) + 2*l);
        float2 Cv = *(const float2*)(bcb + (size_t)t*(2*DSTATE) + DSTATE + 2*l);
        float xdt = xc * dtm;
        h0 = __expf(dtm*A0)*h0 + xdt*Bv.x;
        h1 = __expf(dtm*A1)*h1 + xdt*Bv.y;
        float yp = h0*Cv.x + h1*Cv.y;
        #pragma unroll
        for (int o=16;o;o>>=1) yp += __shfl_xor_sync(~0u, yp, o);
        if (l == 0){
            float z  = g_xz[(base+t)*(2*D_INNER) + D_INNER + i];
            float sz = z / (1.f + __expf(-z));
            g_ygh[(base+t)*K_BIG + i] = __float2half((yp + Dp*xc) * sz);
        }
    }
}

// ---------------- launch ----------------
extern "C" void kernel_launch(void* const* d_in, const int* in_sizes, int n_in,
                              void* d_out, int out_size) {
    const float* x      = (const float*)d_in[0];
    const float* W_in   = (const float*)d_in[1];
    const float* conv_w = (const float*)d_in[2];
    const float* conv_b = (const float*)d_in[3];
    const float* W_x    = (const float*)d_in[4];
    const float* W_dt   = (const float*)d_in[5];
    const float* b_dt   = (const float*)d_in[6];
    const float* A_log  = (const float*)d_in[7];
    const float* D_par  = (const float*)d_in[8];
    const float* W_out  = (const float*)d_in[9];
    const float* ln_g   = (const float*)d_in[10];
    const float* ln_b   = (const float*)d_in[11];
    float* out = (float*)d_out;

    k_tr_in <<<dim3(N_IN/32,    K_IN/32),  256>>>(W_in);
    k_tr_x  <<<dim3(128/32,     K_BIG/32), 256>>>(W_x);
    k_tr_dt <<<dim3(D_INNER/32, K_BIG/32), 256>>>(W_dt);
    k_tr_out<<<dim3(D_MODEL/32, K_BIG/32), 256>>>(W_out);

    k_ln<<<ROWS, 256>>>(x, ln_g, ln_b);
    k_bgemm_in<<<dim3(N_IN/128, ROWS/128), 128>>>();
    k_conv<<<(ROWS*D_INNER)/256, 256>>>(conv_w, conv_b);
    k_bgemm_bcdt<<<dim3(N_BCDT/128, ROWS/128), 128>>>(b_dt);
    k_scan<<<(NB*D_INNER)/8, 256>>>(A_log, D_par);
    k_bgemm_out<<<dim3(D_MODEL/128, ROWS/128), 128>>>(x, out);
}